// round 6
// baseline (speedup 1.0000x reference)
#include <cuda_runtime.h>
#include <cuda_bf16.h>
#include <cstdint>

// Problem constants
constexpr int Bc  = 4;
constexpr int Sc  = 2048;
constexpr int Dc  = 1024;
constexpr int Hc  = 16;
constexpr int HDc = 64;
constexpr int TD3 = 3 * Dc;          // 3072
constexpr int Mrows = Bc * Sc;       // 8192

// Scratch (device globals; no allocation in kernel_launch)
__device__ float g_qkv[(size_t)Mrows * TD3];
__device__ float g_vals[(size_t)Mrows * Dc];
__device__ float g_attn_fb[(size_t)Bc * Hc * Sc * Sc];
// bf16 hi/lo pre-split operands
__device__ __nv_bfloat16 g_x_hi[(size_t)Mrows * Dc],  g_x_lo[(size_t)Mrows * Dc];
__device__ __nv_bfloat16 g_wq_hi[(size_t)TD3 * Dc],   g_wq_lo[(size_t)TD3 * Dc];
__device__ __nv_bfloat16 g_wo_hi[(size_t)Dc * Dc],    g_wo_lo[(size_t)Dc * Dc];
__device__ __nv_bfloat16 g_v_hi[(size_t)Mrows * Dc],  g_v_lo[(size_t)Mrows * Dc];

// ---------------------------------------------------------------------------
// helpers
// ---------------------------------------------------------------------------
__device__ __forceinline__ uint32_t smem_u32(const void* p) {
    uint32_t a;
    asm("{ .reg .u64 t; cvta.to.shared.u64 t, %1; cvt.u32.u64 %0, t; }"
        : "=r"(a) : "l"(p));
    return a;
}
__device__ __forceinline__ uint32_t sw64(uint32_t o)  { return o ^ ((o >> 3) & 0x30); }
__device__ __forceinline__ uint32_t sw128(uint32_t o) { return o ^ ((o >> 3) & 0x70); }

__device__ __forceinline__ void ldsm4(uint32_t a, uint32_t r[4]) {
    asm volatile("ldmatrix.sync.aligned.m8n8.x4.shared.b16 {%0,%1,%2,%3}, [%4];"
                 : "=r"(r[0]), "=r"(r[1]), "=r"(r[2]), "=r"(r[3]) : "r"(a));
}
__device__ __forceinline__ void ldsm4t(uint32_t a, uint32_t r[4]) {
    asm volatile("ldmatrix.sync.aligned.m8n8.x4.trans.shared.b16 {%0,%1,%2,%3}, [%4];"
                 : "=r"(r[0]), "=r"(r[1]), "=r"(r[2]), "=r"(r[3]) : "r"(a));
}
__device__ __forceinline__ void mma16816(float d[4], const uint32_t a[4], const uint32_t b[2]) {
    asm volatile(
        "mma.sync.aligned.m16n8k16.row.col.f32.bf16.bf16.f32 "
        "{%0,%1,%2,%3}, {%4,%5,%6,%7}, {%8,%9}, {%0,%1,%2,%3};"
        : "+f"(d[0]), "+f"(d[1]), "+f"(d[2]), "+f"(d[3])
        : "r"(a[0]), "r"(a[1]), "r"(a[2]), "r"(a[3]), "r"(b[0]), "r"(b[1]));
}
__device__ __forceinline__ void cp16(uint32_t dst, const void* src) {
    asm volatile("cp.async.cg.shared.global [%0], [%1], 16;" :: "r"(dst), "l"(src));
}
__device__ __forceinline__ void cp_commit() {
    asm volatile("cp.async.commit_group;" ::: "memory");
}
template <int N> __device__ __forceinline__ void cp_wait() {
    asm volatile("cp.async.wait_group %0;" :: "n"(N) : "memory");
}

// fp32 float4 -> hi/lo bf16x4 (8B each)
__device__ __forceinline__ void split_hilo(float4 v, uint2& hw, uint2& lw) {
    __nv_bfloat162 h01 = __floats2bfloat162_rn(v.x, v.y);
    __nv_bfloat162 h23 = __floats2bfloat162_rn(v.z, v.w);
    float r0 = v.x - __low2float(h01);
    float r1 = v.y - __high2float(h01);
    float r2 = v.z - __low2float(h23);
    float r3 = v.w - __high2float(h23);
    __nv_bfloat162 l01 = __floats2bfloat162_rn(r0, r1);
    __nv_bfloat162 l23 = __floats2bfloat162_rn(r2, r3);
    hw.x = *reinterpret_cast<uint32_t*>(&h01); hw.y = *reinterpret_cast<uint32_t*>(&h23);
    lw.x = *reinterpret_cast<uint32_t*>(&l01); lw.y = *reinterpret_cast<uint32_t*>(&l23);
}

// ---------------------------------------------------------------------------
// convert kernel: fp32 -> (hi, lo) bf16 arrays
// ---------------------------------------------------------------------------
__global__ __launch_bounds__(256) void cvt_hilo(
    const float4* __restrict__ in, uint2* __restrict__ hi, uint2* __restrict__ lo, int n4)
{
    int i = blockIdx.x * 256 + threadIdx.x;
    if (i < n4) {
        uint2 h, l;
        split_hilo(in[i], h, l);
        hi[i] = h; lo[i] = l;
    }
}

// ---------------------------------------------------------------------------
// compute core: one BK=32 chunk; A,B tiles 128 rows x 64B, SW64
// stage layout: Ah @ +0, Al @ +8192, Bh @ +16384, Bl @ +24576
// ---------------------------------------------------------------------------
__device__ __forceinline__ void compute64(uint32_t sb, int wm, int wn, int lane,
                                          float acc[2][8][4]) {
    const uint32_t Ah = sb, Al = sb + 8192, Bh = sb + 16384, Bl = sb + 24576;
    const int arow = ((lane >> 3) & 1) * 8 + (lane & 7);
    const int brow = ((lane >> 4) & 1) * 8 + (lane & 7);
#pragma unroll
    for (int ks = 0; ks < 2; ks++) {
        const uint32_t akb = ks * 32 + ((lane >> 4) & 1) * 16;
        const uint32_t bkb = ks * 32 + ((lane >> 3) & 1) * 16;
        uint32_t ah[2][4], al[2][4];
#pragma unroll
        for (int mt = 0; mt < 2; mt++) {
            const uint32_t off = sw64((uint32_t)(wm + mt * 16 + arow) * 64 + akb);
            ldsm4(Ah + off, ah[mt]);
            ldsm4(Al + off, al[mt]);
        }
        uint32_t bh[8][2], bl[8][2];
#pragma unroll
        for (int p = 0; p < 4; p++) {
            const uint32_t off = sw64((uint32_t)(wn + p * 16 + brow) * 64 + bkb);
            uint32_t t[4];
            ldsm4(Bh + off, t);
            bh[2*p][0] = t[0]; bh[2*p][1] = t[1]; bh[2*p+1][0] = t[2]; bh[2*p+1][1] = t[3];
            ldsm4(Bl + off, t);
            bl[2*p][0] = t[0]; bl[2*p][1] = t[1]; bl[2*p+1][0] = t[2]; bl[2*p+1][1] = t[3];
        }
#pragma unroll
        for (int nt = 0; nt < 8; nt++) {
#pragma unroll
            for (int mt = 0; mt < 2; mt++) {
                mma16816(acc[mt][nt], ah[mt], bh[nt]);
                mma16816(acc[mt][nt], ah[mt], bl[nt]);
                mma16816(acc[mt][nt], al[mt], bh[nt]);
            }
        }
    }
}

// cp.async one 128x32 bf16 tile (8KB) from [rows x K] bf16 src into SW64 smem
__device__ __forceinline__ void cp_tile(uint32_t dst_base, const __nv_bfloat16* __restrict__ src,
                                        int K, int k0, int tid)
{
#pragma unroll
    for (int i = 0; i < 2; i++) {
        const int id = tid + 256 * i;
        const int row = id >> 2, c16 = id & 3;
        cp16(dst_base + sw64((uint32_t)row * 64 + c16 * 16),
             src + (size_t)row * K + k0 + c16 * 8);
    }
}

// ---------------------------------------------------------------------------
// GEMM: C[128x128] = A @ B^T + bias; A,B pre-split bf16 hi/lo, cp.async 6-stage
// grid (N/128, M/128); smem 6 x 32KB
// ---------------------------------------------------------------------------
constexpr int GSTG = 6;
__global__ __launch_bounds__(256, 1) void gemm_bf16(
    const __nv_bfloat16* __restrict__ Ahg, const __nv_bfloat16* __restrict__ Alg,
    const __nv_bfloat16* __restrict__ Bhg, const __nv_bfloat16* __restrict__ Blg,
    int K, float* __restrict__ C, int N, const float* __restrict__ bias)
{
    extern __shared__ uint8_t sm[];
    const uint32_t sb0 = smem_u32(sm);
    const int tid = threadIdx.x, lane = tid & 31, w = tid >> 5;
    const int wm = (w & 3) * 32, wn = (w >> 2) * 64;

    Ahg += (size_t)(blockIdx.y * 128) * K;
    Alg += (size_t)(blockIdx.y * 128) * K;
    Bhg += (size_t)(blockIdx.x * 128) * K;
    Blg += (size_t)(blockIdx.x * 128) * K;

    const int NC = K >> 5;
#pragma unroll 1
    for (int s = 0; s < 5; s++) {
        const uint32_t st = sb0 + (uint32_t)s * 32768;
        cp_tile(st,          Ahg, K, s * 32, tid);
        cp_tile(st + 8192,   Alg, K, s * 32, tid);
        cp_tile(st + 16384,  Bhg, K, s * 32, tid);
        cp_tile(st + 24576,  Blg, K, s * 32, tid);
        cp_commit();
    }

    float acc[2][8][4] = {};
#pragma unroll 1
    for (int c = 0; c < NC; c++) {
        cp_wait<4>();
        __syncthreads();
        if (c + 5 < NC) {
            const uint32_t st = sb0 + (uint32_t)((c + 5) % GSTG) * 32768;
            cp_tile(st,          Ahg, K, (c + 5) * 32, tid);
            cp_tile(st + 8192,   Alg, K, (c + 5) * 32, tid);
            cp_tile(st + 16384,  Bhg, K, (c + 5) * 32, tid);
            cp_tile(st + 24576,  Blg, K, (c + 5) * 32, tid);
        }
        cp_commit();
        compute64(sb0 + (uint32_t)(c % GSTG) * 32768, wm, wn, lane, acc);
    }

    const int gr = blockIdx.y * 128 + wm + (lane >> 2);
    const int gc = blockIdx.x * 128 + wn + (lane & 3) * 2;
#pragma unroll
    for (int mt = 0; mt < 2; mt++) {
        const int r0 = gr + mt * 16;
#pragma unroll
        for (int nt = 0; nt < 8; nt++) {
            const int cc = gc + nt * 8;
            const float b0 = __ldg(bias + cc), b1 = __ldg(bias + cc + 1);
            float2 v0 = {acc[mt][nt][0] + b0, acc[mt][nt][1] + b1};
            float2 v1 = {acc[mt][nt][2] + b0, acc[mt][nt][3] + b1};
            *reinterpret_cast<float2*>(C + (size_t)r0 * N + cc) = v0;
            *reinterpret_cast<float2*>(C + (size_t)(r0 + 8) * N + cc) = v1;
        }
    }
}

// ---------------------------------------------------------------------------
// Scores kernel: S = (Q.K^T)*0.125; K-dim 64 single-shot; 2 CTAs/SM
// smem 64KB: Qh 0, Ql 16K, Kh 32K, Kl 48K  (128 rows x 128B SW128)
// ---------------------------------------------------------------------------
__device__ __forceinline__ void load128x64(uint8_t* sm, uint32_t hi, uint32_t lo,
                                           const float* __restrict__ src, int ld, int tid)
{
    const int row = tid >> 1;
    const int ch  = tid & 1;
    const float4* p = reinterpret_cast<const float4*>(src + (size_t)row * ld + ch * 32);
    const uint32_t base = (uint32_t)row * 128 + (uint32_t)ch * 64;
#pragma unroll
    for (int i = 0; i < 8; i++) {
        uint2 hw, lw;
        split_hilo(p[i], hw, lw);
        const uint32_t sw = sw128(base + i * 8);
        *reinterpret_cast<uint2*>(sm + hi + sw) = hw;
        *reinterpret_cast<uint2*>(sm + lo + sw) = lw;
    }
}

__global__ __launch_bounds__(256, 2) void scores_mma(
    const float* __restrict__ qkv, float* __restrict__ attn)
{
    extern __shared__ uint8_t sm[];
    const uint32_t sb0 = smem_u32(sm);
    const int tid = threadIdx.x, lane = tid & 31, w = tid >> 5;
    const int wm = (w & 3) * 32, wn = (w >> 2) * 64;

    const int z = blockIdx.z, b = z >> 4, h = z & 15;
    const float* Qs = qkv + (size_t)b * Sc * TD3 + h * 192
                    + (size_t)(blockIdx.y * 128) * TD3;
    const float* Ks = qkv + (size_t)b * Sc * TD3 + h * 192 + 64
                    + (size_t)(blockIdx.x * 128) * TD3;

    load128x64(sm, 0,     16384, Qs, TD3, tid);
    load128x64(sm, 32768, 49152, Ks, TD3, tid);
    __syncthreads();

    float acc[2][8][4] = {};
    {
        const uint32_t Ah = sb0, Al = sb0 + 16384, Bh = sb0 + 32768, Bl = sb0 + 49152;
        const int arow = ((lane >> 3) & 1) * 8 + (lane & 7);
        const int brow = ((lane >> 4) & 1) * 8 + (lane & 7);
#pragma unroll
        for (int ks = 0; ks < 4; ks++) {
            const uint32_t akb = ks * 32 + ((lane >> 4) & 1) * 16;
            const uint32_t bkb = ks * 32 + ((lane >> 3) & 1) * 16;
            uint32_t ah[2][4], al[2][4];
#pragma unroll
            for (int mt = 0; mt < 2; mt++) {
                const uint32_t off = sw128((uint32_t)(wm + mt * 16 + arow) * 128 + akb);
                ldsm4(Ah + off, ah[mt]);
                ldsm4(Al + off, al[mt]);
            }
            uint32_t bh[8][2], bl[8][2];
#pragma unroll
            for (int p = 0; p < 4; p++) {
                const uint32_t off = sw128((uint32_t)(wn + p * 16 + brow) * 128 + bkb);
                uint32_t t[4];
                ldsm4(Bh + off, t);
                bh[2*p][0] = t[0]; bh[2*p][1] = t[1]; bh[2*p+1][0] = t[2]; bh[2*p+1][1] = t[3];
                ldsm4(Bl + off, t);
                bl[2*p][0] = t[0]; bl[2*p][1] = t[1]; bl[2*p+1][0] = t[2]; bl[2*p+1][1] = t[3];
            }
#pragma unroll
            for (int nt = 0; nt < 8; nt++) {
#pragma unroll
                for (int mt = 0; mt < 2; mt++) {
                    mma16816(acc[mt][nt], ah[mt], bh[nt]);
                    mma16816(acc[mt][nt], ah[mt], bl[nt]);
                    mma16816(acc[mt][nt], al[mt], bh[nt]);
                }
            }
        }
    }
    __syncthreads();

    // stage scaled result in smem (64KB fp32), then coalesced copy out
    float* smf = reinterpret_cast<float*>(sm);
    const int r0 = wm + (lane >> 2);
    const int c0 = wn + (lane & 3) * 2;
#pragma unroll
    for (int mt = 0; mt < 2; mt++) {
#pragma unroll
        for (int nt = 0; nt < 8; nt++) {
            const int cc = c0 + nt * 8;
            float2 v0 = {acc[mt][nt][0] * 0.125f, acc[mt][nt][1] * 0.125f};
            float2 v1 = {acc[mt][nt][2] * 0.125f, acc[mt][nt][3] * 0.125f};
            *reinterpret_cast<float2*>(smf + (r0 + mt * 16) * 128 + cc) = v0;
            *reinterpret_cast<float2*>(smf + (r0 + mt * 16 + 8) * 128 + cc) = v1;
        }
    }
    __syncthreads();

    float* cbase = attn + (size_t)z * Sc * Sc + (size_t)(blockIdx.y * 128) * Sc
                 + blockIdx.x * 128;
    const float4* s4 = reinterpret_cast<const float4*>(sm);
#pragma unroll
    for (int i = 0; i < 16; i++) {
        const int id = tid + 256 * i;
        const int row = id >> 5, u = id & 31;
        *reinterpret_cast<float4*>(cbase + (size_t)row * Sc + u * 4) = s4[id];
    }
}

// ---------------------------------------------------------------------------
// PV kernel (unchanged from R4, verified correct)
// ---------------------------------------------------------------------------
__device__ __forceinline__ void ldg16(const float* __restrict__ src, int ld, int tid, float4 r[4]) {
    const float4* p = reinterpret_cast<const float4*>(src + (size_t)(tid >> 1) * ld + (tid & 1) * 16);
#pragma unroll
    for (int i = 0; i < 4; i++) r[i] = p[i];
}
__device__ __forceinline__ void cvt_sts(uint8_t* sm, uint32_t hi, uint32_t lo,
                                        uint32_t swoff, float4 v) {
    uint2 hw, lw;
    split_hilo(v, hw, lw);
    *reinterpret_cast<uint2*>(sm + hi + swoff) = hw;
    *reinterpret_cast<uint2*>(sm + lo + swoff) = lw;
}
__device__ __forceinline__ void sts16(uint8_t* sm, uint32_t hi, uint32_t lo, int tid, const float4 r[4]) {
    const uint32_t base = (uint32_t)(tid >> 1) * 64 + (uint32_t)(tid & 1) * 32;
#pragma unroll
    for (int i = 0; i < 4; i++) cvt_sts(sm, hi, lo, sw64(base + i * 8), r[i]);
}
__device__ __forceinline__ void ldgV(const float* __restrict__ src, int tid, float4 r[2]) {
    const float4* p = reinterpret_cast<const float4*>(src + (size_t)(tid >> 3) * TD3 + (tid & 7) * 8);
    r[0] = p[0]; r[1] = p[1];
}
__device__ __forceinline__ void stsV(uint8_t* sm, uint32_t hi, uint32_t lo, int tid, const float4 r[2]) {
    const uint32_t base = (uint32_t)(tid >> 3) * 128 + (uint32_t)(tid & 7) * 16;
    cvt_sts(sm, hi, lo, sw128(base), r[0]);
    cvt_sts(sm, hi, lo, sw128(base + 8), r[1]);
}
__device__ __forceinline__ void computePV(uint32_t sb, int wm, int wn, int lane,
                                          float acc[2][4][4]) {
    const uint32_t Ah = sb, Al = sb + 8192, Vh = sb + 16384, Vl = sb + 20480;
    const int arow = ((lane >> 3) & 1) * 8 + (lane & 7);
    const int krw  = ((lane >> 3) & 1) * 8 + (lane & 7);
    const int dof  = ((lane >> 4) & 1) * 8;
#pragma unroll
    for (int ks = 0; ks < 2; ks++) {
        const uint32_t akb = ks * 32 + ((lane >> 4) & 1) * 16;
        uint32_t ah[2][4], al[2][4];
#pragma unroll
        for (int mt = 0; mt < 2; mt++) {
            const uint32_t off = sw64((uint32_t)(wm + mt * 16 + arow) * 64 + akb);
            ldsm4(Ah + off, ah[mt]);
            ldsm4(Al + off, al[mt]);
        }
        uint32_t vh[4][2], vl[4][2];
#pragma unroll
        for (int p = 0; p < 2; p++) {
            const uint32_t off = sw128((uint32_t)(ks * 16 + krw) * 128 +
                                       (uint32_t)(wn + p * 16 + dof) * 2);
            uint32_t t[4];
            ldsm4t(Vh + off, t);
            vh[2*p][0] = t[0]; vh[2*p][1] = t[1]; vh[2*p+1][0] = t[2]; vh[2*p+1][1] = t[3];
            ldsm4t(Vl + off, t);
            vl[2*p][0] = t[0]; vl[2*p][1] = t[1]; vl[2*p+1][0] = t[2]; vl[2*p+1][1] = t[3];
        }
#pragma unroll
        for (int nt = 0; nt < 4; nt++) {
#pragma unroll
            for (int mt = 0; mt < 2; mt++) {
                mma16816(acc[mt][nt], ah[mt], vh[nt]);
                mma16816(acc[mt][nt], ah[mt], vl[nt]);
                mma16816(acc[mt][nt], al[mt], vh[nt]);
            }
        }
    }
}

__global__ __launch_bounds__(256, 1) void pv_mma(
    const float* __restrict__ attn, const float* __restrict__ qkv,
    float* __restrict__ vals)
{
    extern __shared__ uint8_t sm[];
    const uint32_t sb0 = smem_u32(sm);
    const int tid = threadIdx.x, lane = tid & 31, w = tid >> 5;
    const int wm = (w & 3) * 32, wn = (w >> 2) * 32;

    const int z = blockIdx.y, b = z >> 4, h = z & 15;
    const float* A = attn + (size_t)z * Sc * Sc + (size_t)(blockIdx.x * 128) * Sc;
    const float* V = qkv + (size_t)b * Sc * TD3 + h * 192 + 128;

    float acc[2][4][4] = {};
    float4 ra[4], rv[2];
    ldg16(A, Sc, tid, ra);
    ldgV(V, tid, rv);

    for (int c = 0; c < 64; c++) {
        const uint32_t buf = (uint32_t)(c & 1) * 24576;
        sts16(sm, buf, buf + 8192, tid, ra);
        stsV(sm, buf + 16384, buf + 20480, tid, rv);
        __syncthreads();
        if (c < 63) {
            ldg16(A + (c + 1) * 32, Sc, tid, ra);
            ldgV(V + (size_t)(c + 1) * 32 * TD3, tid, rv);
        }
        computePV(sb0 + buf, wm, wn, lane, acc);
        __syncthreads();
    }

    float* Co = vals + (size_t)z * Sc * HDc + (size_t)(blockIdx.x * 128) * HDc;
    const int r0b = wm + (lane >> 2);
    const int ccb = wn + (lane & 3) * 2;
#pragma unroll
    for (int mt = 0; mt < 2; mt++) {
        const int r0 = r0b + mt * 16;
#pragma unroll
        for (int nt = 0; nt < 4; nt++) {
            const int cc = ccb + nt * 8;
            float2 v0 = {acc[mt][nt][0], acc[mt][nt][1]};
            float2 v1 = {acc[mt][nt][2], acc[mt][nt][3]};
            *reinterpret_cast<float2*>(Co + (size_t)r0 * HDc + cc) = v0;
            *reinterpret_cast<float2*>(Co + (size_t)(r0 + 8) * HDc + cc) = v1;
        }
    }
}

// ---------------------------------------------------------------------------
// Row softmax in-place
// ---------------------------------------------------------------------------
__global__ __launch_bounds__(256) void row_softmax(float* __restrict__ attn)
{
    __shared__ float red[8];
    const int t = threadIdx.x;
    float4* row = reinterpret_cast<float4*>(attn + (size_t)blockIdx.x * Sc);
    float4 v0 = row[t];
    float4 v1 = row[t + 256];

    float m = fmaxf(fmaxf(fmaxf(v0.x, v0.y), fmaxf(v0.z, v0.w)),
                    fmaxf(fmaxf(v1.x, v1.y), fmaxf(v1.z, v1.w)));
#pragma unroll
    for (int o = 16; o; o >>= 1) m = fmaxf(m, __shfl_xor_sync(0xFFFFFFFFu, m, o));
    if ((t & 31) == 0) red[t >> 5] = m;
    __syncthreads();
    m = red[0];
#pragma unroll
    for (int i = 1; i < 8; i++) m = fmaxf(m, red[i]);
    __syncthreads();

    v0.x = __expf(v0.x - m); v0.y = __expf(v0.y - m);
    v0.z = __expf(v0.z - m); v0.w = __expf(v0.w - m);
    v1.x = __expf(v1.x - m); v1.y = __expf(v1.y - m);
    v1.z = __expf(v1.z - m); v1.w = __expf(v1.w - m);
    float s = (v0.x + v0.y) + (v0.z + v0.w) + (v1.x + v1.y) + (v1.z + v1.w);
#pragma unroll
    for (int o = 16; o; o >>= 1) s += __shfl_xor_sync(0xFFFFFFFFu, s, o);
    if ((t & 31) == 0) red[t >> 5] = s;
    __syncthreads();
    s = red[0];
#pragma unroll
    for (int i = 1; i < 8; i++) s += red[i];
    const float inv = 1.f / s;

    v0.x *= inv; v0.y *= inv; v0.z *= inv; v0.w *= inv;
    v1.x *= inv; v1.y *= inv; v1.z *= inv; v1.w *= inv;
    row[t] = v0;
    row[t + 256] = v1;
}

// ---------------------------------------------------------------------------
extern "C" void kernel_launch(void* const* d_in, const int* in_sizes, int n_in,
                              void* d_out, int out_size)
{
    const float* x     = (const float*)d_in[0];
    const float* w_qkv = (const float*)d_in[1];
    const float* b_qkv = (const float*)d_in[2];
    const float* w_out = (const float*)d_in[3];
    const float* b_out = (const float*)d_in[4];
    float* out = (float*)d_out;

    const size_t BSD  = (size_t)Bc * Sc * Dc;
    const size_t BHSS = (size_t)Bc * Hc * Sc * Sc;

    float *qkv, *vals, *attn_fb;
    cudaGetSymbolAddress((void**)&qkv,     g_qkv);
    cudaGetSymbolAddress((void**)&vals,    g_vals);
    cudaGetSymbolAddress((void**)&attn_fb, g_attn_fb);
    __nv_bfloat16 *xh, *xl, *wqh, *wql, *woh, *wol, *vh, *vl;
    cudaGetSymbolAddress((void**)&xh,  g_x_hi);  cudaGetSymbolAddress((void**)&xl,  g_x_lo);
    cudaGetSymbolAddress((void**)&wqh, g_wq_hi); cudaGetSymbolAddress((void**)&wql, g_wq_lo);
    cudaGetSymbolAddress((void**)&woh, g_wo_hi); cudaGetSymbolAddress((void**)&wol, g_wo_lo);
    cudaGetSymbolAddress((void**)&vh,  g_v_hi);  cudaGetSymbolAddress((void**)&vl,  g_v_lo);

    float* attn = ((size_t)out_size >= BSD + BHSS) ? (out + BSD) : attn_fb;

    cudaFuncSetAttribute(gemm_bf16,  cudaFuncAttributeMaxDynamicSharedMemorySize, GSTG * 32768);
    cudaFuncSetAttribute(scores_mma, cudaFuncAttributeMaxDynamicSharedMemorySize, 65536);
    cudaFuncSetAttribute(pv_mma,     cudaFuncAttributeMaxDynamicSharedMemorySize, 49152);

    // 0) pre-split fp32 -> bf16 hi/lo
    cvt_hilo<<<(int)(BSD / 4 / 256), 256>>>((const float4*)x, (uint2*)xh, (uint2*)xl, (int)(BSD / 4));
    cvt_hilo<<<(int)((size_t)TD3 * Dc / 4 / 256), 256>>>((const float4*)w_qkv, (uint2*)wqh, (uint2*)wql, (int)((size_t)TD3 * Dc / 4));
    cvt_hilo<<<(int)((size_t)Dc * Dc / 4 / 256), 256>>>((const float4*)w_out, (uint2*)woh, (uint2*)wol, (int)((size_t)Dc * Dc / 4));

    // 1) fused QKV projection: [8192,3072] = x @ w_qkv^T + b_qkv
    gemm_bf16<<<dim3(TD3 / 128, Mrows / 128), 256, GSTG * 32768>>>(
        xh, xl, wqh, wql, Dc, qkv, TD3, b_qkv);

    // 2) attention scores (scaled by 1/8)
    scores_mma<<<dim3(Sc / 128, Sc / 128, Bc * Hc), 256, 65536>>>(qkv, attn);

    // 3) softmax rows in place
    row_softmax<<<Bc * Hc * Sc, 256>>>(attn);

    // 4) PV
    pv_mma<<<dim3(Sc / 128, Bc * Hc), 256, 49152>>>(attn, qkv, vals);

    // 5) split vals, then output projection: out = vals @ w_out^T + b_out
    cvt_hilo<<<(int)(BSD / 4 / 256), 256>>>((const float4*)vals, (uint2*)vh, (uint2*)vl, (int)(BSD / 4));
    gemm_bf16<<<dim3(Dc / 128, Mrows / 128), 256, GSTG * 32768>>>(
        vh, vl, woh, wol, Dc, out, Dc, b_out);
}

// round 7
// speedup vs baseline: 1.2167x; 1.2167x over previous
#include <cuda_runtime.h>
#include <cuda_bf16.h>
#include <cstdint>

// Problem constants
constexpr int Bc  = 4;
constexpr int Sc  = 2048;
constexpr int Dc  = 1024;
constexpr int Hc  = 16;
constexpr int HDc = 64;
constexpr int TD3 = 3 * Dc;          // 3072
constexpr int Mrows = Bc * Sc;       // 8192

// Scratch (device globals; no allocation in kernel_launch)
__device__ float g_attn_fb[(size_t)Bc * Hc * Sc * Sc];
__device__ float g_psum[(size_t)Bc * Hc * Sc * 16];
__device__ __nv_bfloat16 g_x_hi[(size_t)Mrows * Dc],   g_x_lo[(size_t)Mrows * Dc];
__device__ __nv_bfloat16 g_wq_hi[(size_t)TD3 * Dc],    g_wq_lo[(size_t)TD3 * Dc];
__device__ __nv_bfloat16 g_wo_hi[(size_t)Dc * Dc],     g_wo_lo[(size_t)Dc * Dc];
__device__ __nv_bfloat16 g_qkv_hi[(size_t)Mrows * TD3], g_qkv_lo[(size_t)Mrows * TD3];
__device__ __nv_bfloat16 g_v_hi[(size_t)Mrows * Dc],   g_v_lo[(size_t)Mrows * Dc];

// ---------------------------------------------------------------------------
// helpers
// ---------------------------------------------------------------------------
__device__ __forceinline__ uint32_t smem_u32(const void* p) {
    uint32_t a;
    asm("{ .reg .u64 t; cvta.to.shared.u64 t, %1; cvt.u32.u64 %0, t; }"
        : "=r"(a) : "l"(p));
    return a;
}
__device__ __forceinline__ uint32_t sw64(uint32_t o)  { return o ^ ((o >> 3) & 0x30); }
__device__ __forceinline__ uint32_t sw128(uint32_t o) { return o ^ ((o >> 3) & 0x70); }

__device__ __forceinline__ void ldsm4(uint32_t a, uint32_t r[4]) {
    asm volatile("ldmatrix.sync.aligned.m8n8.x4.shared.b16 {%0,%1,%2,%3}, [%4];"
                 : "=r"(r[0]), "=r"(r[1]), "=r"(r[2]), "=r"(r[3]) : "r"(a));
}
__device__ __forceinline__ void ldsm4t(uint32_t a, uint32_t r[4]) {
    asm volatile("ldmatrix.sync.aligned.m8n8.x4.trans.shared.b16 {%0,%1,%2,%3}, [%4];"
                 : "=r"(r[0]), "=r"(r[1]), "=r"(r[2]), "=r"(r[3]) : "r"(a));
}
__device__ __forceinline__ void mma16816(float d[4], const uint32_t a[4], const uint32_t b[2]) {
    asm volatile(
        "mma.sync.aligned.m16n8k16.row.col.f32.bf16.bf16.f32 "
        "{%0,%1,%2,%3}, {%4,%5,%6,%7}, {%8,%9}, {%0,%1,%2,%3};"
        : "+f"(d[0]), "+f"(d[1]), "+f"(d[2]), "+f"(d[3])
        : "r"(a[0]), "r"(a[1]), "r"(a[2]), "r"(a[3]), "r"(b[0]), "r"(b[1]));
}
__device__ __forceinline__ void cp16(uint32_t dst, const void* src) {
    asm volatile("cp.async.cg.shared.global [%0], [%1], 16;" :: "r"(dst), "l"(src));
}
__device__ __forceinline__ void cp_commit() {
    asm volatile("cp.async.commit_group;" ::: "memory");
}
template <int N> __device__ __forceinline__ void cp_wait() {
    asm volatile("cp.async.wait_group %0;" :: "n"(N) : "memory");
}
__device__ __forceinline__ void split_hilo(float4 v, uint2& hw, uint2& lw) {
    __nv_bfloat162 h01 = __floats2bfloat162_rn(v.x, v.y);
    __nv_bfloat162 h23 = __floats2bfloat162_rn(v.z, v.w);
    float r0 = v.x - __low2float(h01);
    float r1 = v.y - __high2float(h01);
    float r2 = v.z - __low2float(h23);
    float r3 = v.w - __high2float(h23);
    __nv_bfloat162 l01 = __floats2bfloat162_rn(r0, r1);
    __nv_bfloat162 l23 = __floats2bfloat162_rn(r2, r3);
    hw.x = *reinterpret_cast<uint32_t*>(&h01); hw.y = *reinterpret_cast<uint32_t*>(&h23);
    lw.x = *reinterpret_cast<uint32_t*>(&l01); lw.y = *reinterpret_cast<uint32_t*>(&l23);
}
__device__ __forceinline__ void pack_hilo(float v0, float v1, uint32_t& h, uint32_t& l) {
    __nv_bfloat162 h2 = __floats2bfloat162_rn(v0, v1);
    float r0 = v0 - __low2float(h2), r1 = v1 - __high2float(h2);
    __nv_bfloat162 l2 = __floats2bfloat162_rn(r0, r1);
    h = *reinterpret_cast<uint32_t*>(&h2);
    l = *reinterpret_cast<uint32_t*>(&l2);
}

// ---------------------------------------------------------------------------
// convert kernel: fp32 -> (hi, lo) bf16 arrays
// ---------------------------------------------------------------------------
__global__ __launch_bounds__(256) void cvt_hilo(
    const float4* __restrict__ in, uint2* __restrict__ hi, uint2* __restrict__ lo, int n4)
{
    int i = blockIdx.x * 256 + threadIdx.x;
    if (i < n4) {
        uint2 h, l;
        split_hilo(in[i], h, l);
        hi[i] = h; lo[i] = l;
    }
}

// ---------------------------------------------------------------------------
// compute core: one BK=32 chunk; A,B tiles 128 rows x 64B, SW64
// low-liveness: B fragments loaded in 4-wide halves
// ---------------------------------------------------------------------------
__device__ __forceinline__ void compute64(uint32_t sb, int wm, int wn, int lane,
                                          float acc[2][8][4]) {
    const uint32_t Ah = sb, Al = sb + 8192, Bh = sb + 16384, Bl = sb + 24576;
    const int arow = ((lane >> 3) & 1) * 8 + (lane & 7);
    const int brow = ((lane >> 4) & 1) * 8 + (lane & 7);
#pragma unroll
    for (int ks = 0; ks < 2; ks++) {
        const uint32_t akb = (uint32_t)(ks * 32 + ((lane >> 4) & 1) * 16);
        const uint32_t bkb = (uint32_t)(ks * 32 + ((lane >> 3) & 1) * 16);
        uint32_t ah[2][4], al[2][4];
#pragma unroll
        for (int mt = 0; mt < 2; mt++) {
            const uint32_t off = sw64((uint32_t)(wm + mt * 16 + arow) * 64 + akb);
            ldsm4(Ah + off, ah[mt]);
            ldsm4(Al + off, al[mt]);
        }
#pragma unroll
        for (int half = 0; half < 2; half++) {
            uint32_t bh[4][2], bl[4][2];
#pragma unroll
            for (int p = 0; p < 2; p++) {
                const uint32_t off = sw64((uint32_t)(wn + (half * 2 + p) * 16 + brow) * 64 + bkb);
                uint32_t t[4];
                ldsm4(Bh + off, t);
                bh[2*p][0]=t[0]; bh[2*p][1]=t[1]; bh[2*p+1][0]=t[2]; bh[2*p+1][1]=t[3];
                ldsm4(Bl + off, t);
                bl[2*p][0]=t[0]; bl[2*p][1]=t[1]; bl[2*p+1][0]=t[2]; bl[2*p+1][1]=t[3];
            }
#pragma unroll
            for (int nt = 0; nt < 4; nt++)
#pragma unroll
                for (int mt = 0; mt < 2; mt++) {
                    mma16816(acc[mt][half*4+nt], ah[mt], bh[nt]);
                    mma16816(acc[mt][half*4+nt], ah[mt], bl[nt]);
                    mma16816(acc[mt][half*4+nt], al[mt], bh[nt]);
                }
        }
    }
}

// cp.async one 128x32 bf16 tile (8KB), SW64 rows
__device__ __forceinline__ void cp_tile(uint32_t dst_base, const __nv_bfloat16* __restrict__ src,
                                        int K, int k0, int tid)
{
#pragma unroll
    for (int i = 0; i < 2; i++) {
        const int id = tid + 256 * i;
        const int row = id >> 2, c16 = id & 3;
        cp16(dst_base + sw64((uint32_t)row * 64 + c16 * 16),
             src + (size_t)row * K + k0 + c16 * 8);
    }
}

// ---------------------------------------------------------------------------
// GEMM: C[128x128] = A @ B^T + bias; 3-stage cp.async, 2 CTAs/SM
// BF16OUT: write (hi,lo) bf16 arrays instead of fp32 C
// ---------------------------------------------------------------------------
template <bool BF16OUT>
__global__ __launch_bounds__(256, 2) void gemm_bf16(
    const __nv_bfloat16* __restrict__ Ahg, const __nv_bfloat16* __restrict__ Alg,
    const __nv_bfloat16* __restrict__ Bhg, const __nv_bfloat16* __restrict__ Blg,
    int K, float* __restrict__ C, __nv_bfloat16* __restrict__ Chi,
    __nv_bfloat16* __restrict__ Clo, int N, const float* __restrict__ bias)
{
    extern __shared__ uint8_t sm[];
    const uint32_t sb0 = smem_u32(sm);
    const int tid = threadIdx.x, lane = tid & 31, w = tid >> 5;
    const int wm = (w & 3) * 32, wn = (w >> 2) * 64;

    Ahg += (size_t)(blockIdx.y * 128) * K;
    Alg += (size_t)(blockIdx.y * 128) * K;
    Bhg += (size_t)(blockIdx.x * 128) * K;
    Blg += (size_t)(blockIdx.x * 128) * K;

    const int NC = K >> 5;
#pragma unroll 1
    for (int s = 0; s < 2; s++) {
        const uint32_t st = sb0 + (uint32_t)s * 32768;
        cp_tile(st,          Ahg, K, s * 32, tid);
        cp_tile(st + 8192,   Alg, K, s * 32, tid);
        cp_tile(st + 16384,  Bhg, K, s * 32, tid);
        cp_tile(st + 24576,  Blg, K, s * 32, tid);
        cp_commit();
    }

    float acc[2][8][4] = {};
#pragma unroll 1
    for (int c = 0; c < NC; c++) {
        cp_wait<1>();
        __syncthreads();
        if (c + 2 < NC) {
            const uint32_t st = sb0 + (uint32_t)((c + 2) % 3) * 32768;
            cp_tile(st,          Ahg, K, (c + 2) * 32, tid);
            cp_tile(st + 8192,   Alg, K, (c + 2) * 32, tid);
            cp_tile(st + 16384,  Bhg, K, (c + 2) * 32, tid);
            cp_tile(st + 24576,  Blg, K, (c + 2) * 32, tid);
        }
        cp_commit();
        compute64(sb0 + (uint32_t)(c % 3) * 32768, wm, wn, lane, acc);
    }

    const int gr = blockIdx.y * 128 + wm + (lane >> 2);
    const int gc = blockIdx.x * 128 + wn + (lane & 3) * 2;
#pragma unroll
    for (int mt = 0; mt < 2; mt++) {
        const int r0 = gr + mt * 16;
#pragma unroll
        for (int nt = 0; nt < 8; nt++) {
            const int cc = gc + nt * 8;
            const float b0 = __ldg(bias + cc), b1 = __ldg(bias + cc + 1);
            const float v00 = acc[mt][nt][0] + b0, v01 = acc[mt][nt][1] + b1;
            const float v10 = acc[mt][nt][2] + b0, v11 = acc[mt][nt][3] + b1;
            if (BF16OUT) {
                uint32_t h, l;
                pack_hilo(v00, v01, h, l);
                *reinterpret_cast<uint32_t*>(Chi + (size_t)r0 * N + cc) = h;
                *reinterpret_cast<uint32_t*>(Clo + (size_t)r0 * N + cc) = l;
                pack_hilo(v10, v11, h, l);
                *reinterpret_cast<uint32_t*>(Chi + (size_t)(r0 + 8) * N + cc) = h;
                *reinterpret_cast<uint32_t*>(Clo + (size_t)(r0 + 8) * N + cc) = l;
            } else {
                float2 u0 = {v00, v01}, u1 = {v10, v11};
                *reinterpret_cast<float2*>(C + (size_t)r0 * N + cc) = u0;
                *reinterpret_cast<float2*>(C + (size_t)(r0 + 8) * N + cc) = u1;
            }
        }
    }
}

// ---------------------------------------------------------------------------
// Scores kernel: attn = exp((Q.K^T)*0.125) (unnormalized) + per-tile row sums.
// Tiles cp.async'd from pre-split bf16 qkv. smem 64KB; 2 CTAs/SM.
// ---------------------------------------------------------------------------
__global__ __launch_bounds__(256, 2) void scores_mma(
    const __nv_bfloat16* __restrict__ qh, const __nv_bfloat16* __restrict__ ql,
    float* __restrict__ attn, float* __restrict__ psum)
{
    extern __shared__ uint8_t sm[];
    const uint32_t sb0 = smem_u32(sm);
    const int tid = threadIdx.x, lane = tid & 31, w = tid >> 5;
    const int wm = (w & 3) * 32, wn = (w >> 2) * 64;
    const int z = blockIdx.z, b = z >> 4, h = z & 15;
    const size_t hb = (size_t)b * Sc * TD3 + h * 192;
    const __nv_bfloat16* Qh = qh + hb + (size_t)(blockIdx.y * 128) * TD3;
    const __nv_bfloat16* Ql = ql + hb + (size_t)(blockIdx.y * 128) * TD3;
    const __nv_bfloat16* Kh = qh + hb + 64 + (size_t)(blockIdx.x * 128) * TD3;
    const __nv_bfloat16* Kl = ql + hb + 64 + (size_t)(blockIdx.x * 128) * TD3;

#pragma unroll
    for (int i = 0; i < 4; i++) {
        const int id = tid + 256 * i;
        const int row = id >> 3, c16 = id & 7;
        const uint32_t d = sw128((uint32_t)row * 128 + c16 * 16);
        const size_t so = (size_t)row * TD3 + c16 * 8;
        cp16(sb0 +         d, Qh + so);
        cp16(sb0 + 16384 + d, Ql + so);
        cp16(sb0 + 32768 + d, Kh + so);
        cp16(sb0 + 49152 + d, Kl + so);
    }
    cp_commit();
    cp_wait<0>();
    __syncthreads();

    float acc[2][8][4] = {};
    {
        const uint32_t Ah = sb0, Al = sb0 + 16384, Bh = sb0 + 32768, Bl = sb0 + 49152;
        const int arow = ((lane >> 3) & 1) * 8 + (lane & 7);
        const int brow = ((lane >> 4) & 1) * 8 + (lane & 7);
#pragma unroll
        for (int ks = 0; ks < 4; ks++) {
            const uint32_t akb = (uint32_t)(ks * 32 + ((lane >> 4) & 1) * 16);
            const uint32_t bkb = (uint32_t)(ks * 32 + ((lane >> 3) & 1) * 16);
            uint32_t ah[2][4], al[2][4];
#pragma unroll
            for (int mt = 0; mt < 2; mt++) {
                const uint32_t off = sw128((uint32_t)(wm + mt * 16 + arow) * 128 + akb);
                ldsm4(Ah + off, ah[mt]);
                ldsm4(Al + off, al[mt]);
            }
#pragma unroll
            for (int half = 0; half < 2; half++) {
                uint32_t bh[4][2], bl[4][2];
#pragma unroll
                for (int p = 0; p < 2; p++) {
                    const uint32_t off = sw128((uint32_t)(wn + (half * 2 + p) * 16 + brow) * 128 + bkb);
                    uint32_t t[4];
                    ldsm4(Bh + off, t);
                    bh[2*p][0]=t[0]; bh[2*p][1]=t[1]; bh[2*p+1][0]=t[2]; bh[2*p+1][1]=t[3];
                    ldsm4(Bl + off, t);
                    bl[2*p][0]=t[0]; bl[2*p][1]=t[1]; bl[2*p+1][0]=t[2]; bl[2*p+1][1]=t[3];
                }
#pragma unroll
                for (int nt = 0; nt < 4; nt++)
#pragma unroll
                    for (int mt = 0; mt < 2; mt++) {
                        mma16816(acc[mt][half*4+nt], ah[mt], bh[nt]);
                        mma16816(acc[mt][half*4+nt], ah[mt], bl[nt]);
                        mma16816(acc[mt][half*4+nt], al[mt], bh[nt]);
                    }
            }
        }
    }
    __syncthreads();

    // exp to smem staging
    float* smf = reinterpret_cast<float*>(sm);
    const int r0 = wm + (lane >> 2);
    const int c0 = wn + (lane & 3) * 2;
#pragma unroll
    for (int mt = 0; mt < 2; mt++) {
#pragma unroll
        for (int nt = 0; nt < 8; nt++) {
            const int cc = c0 + nt * 8;
            smf[(r0 + mt * 16) * 128 + cc]     = __expf(acc[mt][nt][0] * 0.125f);
            smf[(r0 + mt * 16) * 128 + cc + 1] = __expf(acc[mt][nt][1] * 0.125f);
            smf[(r0 + mt * 16 + 8) * 128 + cc]     = __expf(acc[mt][nt][2] * 0.125f);
            smf[(r0 + mt * 16 + 8) * 128 + cc + 1] = __expf(acc[mt][nt][3] * 0.125f);
        }
    }
    __syncthreads();

    // per-row partial sums (staggered, conflict-free)
    if (tid < 128) {
        float s = 0.f;
#pragma unroll 8
        for (int j = 0; j < 128; j++) s += smf[tid * 128 + ((j + tid) & 127)];
        psum[((size_t)z * Sc + blockIdx.y * 128 + tid) * 16 + blockIdx.x] = s;
    }

    float* cbase = attn + (size_t)z * Sc * Sc + (size_t)(blockIdx.y * 128) * Sc
                 + blockIdx.x * 128;
    const float4* s4 = reinterpret_cast<const float4*>(sm);
#pragma unroll
    for (int i = 0; i < 16; i++) {
        const int id = tid + 256 * i;
        const int row = id >> 5, u = id & 31;
        *reinterpret_cast<float4*>(cbase + (size_t)row * Sc + u * 4) = s4[id];
    }
}

// ---------------------------------------------------------------------------
// PV: normalize attn (writeback) + vals = attn_norm @ V ; writes v hi/lo bf16
// ---------------------------------------------------------------------------
__device__ __forceinline__ void computePV(uint32_t sb, int wm, int wn, int lane,
                                          float acc[2][4][4]) {
    const uint32_t Ah = sb, Al = sb + 8192, Vh = sb + 16384, Vl = sb + 20480;
    const int arow = ((lane >> 3) & 1) * 8 + (lane & 7);
    const int krw  = ((lane >> 3) & 1) * 8 + (lane & 7);
    const int dof  = ((lane >> 4) & 1) * 8;
#pragma unroll
    for (int ks = 0; ks < 2; ks++) {
        const uint32_t akb = (uint32_t)(ks * 32 + ((lane >> 4) & 1) * 16);
        uint32_t ah[2][4], al[2][4];
#pragma unroll
        for (int mt = 0; mt < 2; mt++) {
            const uint32_t off = sw64((uint32_t)(wm + mt * 16 + arow) * 64 + akb);
            ldsm4(Ah + off, ah[mt]);
            ldsm4(Al + off, al[mt]);
        }
        uint32_t vh[4][2], vl[4][2];
#pragma unroll
        for (int p = 0; p < 2; p++) {
            const uint32_t off = sw128((uint32_t)(ks * 16 + krw) * 128 +
                                       (uint32_t)(wn + p * 16 + dof) * 2);
            uint32_t t[4];
            ldsm4t(Vh + off, t);
            vh[2*p][0]=t[0]; vh[2*p][1]=t[1]; vh[2*p+1][0]=t[2]; vh[2*p+1][1]=t[3];
            ldsm4t(Vl + off, t);
            vl[2*p][0]=t[0]; vl[2*p][1]=t[1]; vl[2*p+1][0]=t[2]; vl[2*p+1][1]=t[3];
        }
#pragma unroll
        for (int nt = 0; nt < 4; nt++)
#pragma unroll
            for (int mt = 0; mt < 2; mt++) {
                mma16816(acc[mt][nt], ah[mt], vh[nt]);
                mma16816(acc[mt][nt], ah[mt], vl[nt]);
                mma16816(acc[mt][nt], al[mt], vh[nt]);
            }
    }
}

__global__ __launch_bounds__(256, 2) void pv_mma(
    float* __restrict__ attn, const __nv_bfloat16* __restrict__ qh,
    const __nv_bfloat16* __restrict__ ql, const float* __restrict__ psum,
    __nv_bfloat16* __restrict__ voh, __nv_bfloat16* __restrict__ vol)
{
    extern __shared__ uint8_t sm[];
    const uint32_t sb0 = smem_u32(sm);
    float* invs = reinterpret_cast<float*>(sm + 49152);
    const int tid = threadIdx.x, lane = tid & 31, w = tid >> 5;
    const int wm = (w & 3) * 32, wn = (w >> 2) * 32;

    const int z = blockIdx.y, b = z >> 4, h = z & 15;
    const int qt = blockIdx.x;
    float* A = attn + (size_t)z * Sc * Sc + (size_t)(qt * 128) * Sc;
    const __nv_bfloat16* Vh = qh + (size_t)b * Sc * TD3 + h * 192 + 128;
    const __nv_bfloat16* Vl = ql + (size_t)b * Sc * TD3 + h * 192 + 128;

    const int vrow = tid >> 3, vc16 = tid & 7;
    const uint32_t vdst = sw128((uint32_t)vrow * 128 + vc16 * 16);

    // prologue
    float4 ra[4];
    {
        const float4* p = reinterpret_cast<const float4*>(A + (size_t)(tid >> 1) * Sc + (tid & 1) * 16);
#pragma unroll
        for (int i = 0; i < 4; i++) ra[i] = p[i];
    }
    {
        const size_t so = (size_t)vrow * TD3 + vc16 * 8;
        cp16(sb0 + 16384 + vdst, Vh + so);
        cp16(sb0 + 20480 + vdst, Vl + so);
        cp_commit();
    }
    if (tid < 128) {
        const float* pp = psum + ((size_t)z * Sc + qt * 128 + tid) * 16;
        float s = 0.f;
#pragma unroll
        for (int j = 0; j < 16; j++) s += pp[j];
        invs[tid] = 1.f / s;
    }
    __syncthreads();

    float acc[2][4][4] = {};
#pragma unroll 1
    for (int c = 0; c < 64; c++) {
        const uint32_t buf = (uint32_t)(c & 1) * 24576;
        // normalize A chunk: STS hi/lo + write normalized attn back
        {
            const float inv = invs[tid >> 1];
            float* Arow = A + (size_t)(tid >> 1) * Sc + (tid & 1) * 16 + c * 32;
            const uint32_t base = (uint32_t)(tid >> 1) * 64 + (uint32_t)(tid & 1) * 32;
#pragma unroll
            for (int i = 0; i < 4; i++) {
                float4 v = ra[i];
                v.x *= inv; v.y *= inv; v.z *= inv; v.w *= inv;
                *reinterpret_cast<float4*>(Arow + i * 4) = v;
                uint2 hw, lw;
                split_hilo(v, hw, lw);
                const uint32_t sw = sw64(base + i * 8);
                *reinterpret_cast<uint2*>(sm + buf + sw) = hw;
                *reinterpret_cast<uint2*>(sm + buf + 8192 + sw) = lw;
            }
        }
        if (c < 63) {
            const uint32_t nb = (uint32_t)((c + 1) & 1) * 24576;
            const size_t so = (size_t)((c + 1) * 32 + vrow) * TD3 + vc16 * 8;
            cp16(sb0 + nb + 16384 + vdst, Vh + so);
            cp16(sb0 + nb + 20480 + vdst, Vl + so);
            cp_commit();
            cp_wait<1>();
        } else {
            cp_wait<0>();
        }
        __syncthreads();
        if (c < 63) {
            const float4* p = reinterpret_cast<const float4*>(
                A + (size_t)(tid >> 1) * Sc + (tid & 1) * 16 + (c + 1) * 32);
#pragma unroll
            for (int i = 0; i < 4; i++) ra[i] = p[i];
        }
        computePV(sb0 + buf, wm, wn, lane, acc);
        __syncthreads();
    }

    __nv_bfloat16* Oh = voh + (size_t)z * Sc * HDc + (size_t)(qt * 128) * HDc;
    __nv_bfloat16* Ol = vol + (size_t)z * Sc * HDc + (size_t)(qt * 128) * HDc;
    const int r0b = wm + (lane >> 2);
    const int ccb = wn + (lane & 3) * 2;
#pragma unroll
    for (int mt = 0; mt < 2; mt++) {
        const int r0 = r0b + mt * 16;
#pragma unroll
        for (int nt = 0; nt < 4; nt++) {
            const int cc = ccb + nt * 8;
            uint32_t hh, ll;
            pack_hilo(acc[mt][nt][0], acc[mt][nt][1], hh, ll);
            *reinterpret_cast<uint32_t*>(Oh + (size_t)r0 * HDc + cc) = hh;
            *reinterpret_cast<uint32_t*>(Ol + (size_t)r0 * HDc + cc) = ll;
            pack_hilo(acc[mt][nt][2], acc[mt][nt][3], hh, ll);
            *reinterpret_cast<uint32_t*>(Oh + (size_t)(r0 + 8) * HDc + cc) = hh;
            *reinterpret_cast<uint32_t*>(Ol + (size_t)(r0 + 8) * HDc + cc) = ll;
        }
    }
}

// ---------------------------------------------------------------------------
extern "C" void kernel_launch(void* const* d_in, const int* in_sizes, int n_in,
                              void* d_out, int out_size)
{
    const float* x     = (const float*)d_in[0];
    const float* w_qkv = (const float*)d_in[1];
    const float* b_qkv = (const float*)d_in[2];
    const float* w_out = (const float*)d_in[3];
    const float* b_out = (const float*)d_in[4];
    float* out = (float*)d_out;

    const size_t BSD  = (size_t)Bc * Sc * Dc;
    const size_t BHSS = (size_t)Bc * Hc * Sc * Sc;

    float *attn_fb, *psum;
    cudaGetSymbolAddress((void**)&attn_fb, g_attn_fb);
    cudaGetSymbolAddress((void**)&psum,    g_psum);
    __nv_bfloat16 *xh, *xl, *wqh, *wql, *woh, *wol, *qkvh, *qkvl, *vh, *vl;
    cudaGetSymbolAddress((void**)&xh,   g_x_hi);   cudaGetSymbolAddress((void**)&xl,   g_x_lo);
    cudaGetSymbolAddress((void**)&wqh,  g_wq_hi);  cudaGetSymbolAddress((void**)&wql,  g_wq_lo);
    cudaGetSymbolAddress((void**)&woh,  g_wo_hi);  cudaGetSymbolAddress((void**)&wol,  g_wo_lo);
    cudaGetSymbolAddress((void**)&qkvh, g_qkv_hi); cudaGetSymbolAddress((void**)&qkvl, g_qkv_lo);
    cudaGetSymbolAddress((void**)&vh,   g_v_hi);   cudaGetSymbolAddress((void**)&vl,   g_v_lo);

    float* attn = ((size_t)out_size >= BSD + BHSS) ? (out + BSD) : attn_fb;

    cudaFuncSetAttribute(gemm_bf16<true>,  cudaFuncAttributeMaxDynamicSharedMemorySize, 98304);
    cudaFuncSetAttribute(gemm_bf16<false>, cudaFuncAttributeMaxDynamicSharedMemorySize, 98304);
    cudaFuncSetAttribute(scores_mma,       cudaFuncAttributeMaxDynamicSharedMemorySize, 65536);
    cudaFuncSetAttribute(pv_mma,           cudaFuncAttributeMaxDynamicSharedMemorySize, 49664);

    // 0) pre-split fp32 -> bf16 hi/lo
    cvt_hilo<<<(int)(BSD / 4 / 256), 256>>>((const float4*)x, (uint2*)xh, (uint2*)xl, (int)(BSD / 4));
    cvt_hilo<<<(int)((size_t)TD3 * Dc / 4 / 256), 256>>>((const float4*)w_qkv, (uint2*)wqh, (uint2*)wql, (int)((size_t)TD3 * Dc / 4));
    cvt_hilo<<<(int)((size_t)Dc * Dc / 4 / 256), 256>>>((const float4*)w_out, (uint2*)woh, (uint2*)wol, (int)((size_t)Dc * Dc / 4));

    // 1) fused QKV projection -> bf16 hi/lo qkv directly
    gemm_bf16<true><<<dim3(TD3 / 128, Mrows / 128), 256, 98304>>>(
        xh, xl, wqh, wql, Dc, nullptr, qkvh, qkvl, TD3, b_qkv);

    // 2) attention scores: exp(QK/8) + per-tile row sums
    scores_mma<<<dim3(Sc / 128, Sc / 128, Bc * Hc), 256, 65536>>>(qkvh, qkvl, attn, psum);

    // 3) PV: normalize attn in place + vals = attn_norm @ V (writes vals hi/lo)
    pv_mma<<<dim3(Sc / 128, Bc * Hc), 256, 49664>>>(attn, qkvh, qkvl, psum, vh, vl);

    // 4) output projection: out = vals @ w_out^T + b_out
    gemm_bf16<false><<<dim3(Dc / 128, Mrows / 128), 256, 98304>>>(
        vh, vl, woh, wol, Dc, out, nullptr, nullptr, Dc, b_out);
}

// round 8
// speedup vs baseline: 1.2747x; 1.0477x over previous
#include <cuda_runtime.h>
#include <cuda_bf16.h>
#include <cstdint>

// Problem constants
constexpr int Bc  = 4;
constexpr int Sc  = 2048;
constexpr int Dc  = 1024;
constexpr int Hc  = 16;
constexpr int HDc = 64;
constexpr int TD3 = 3 * Dc;          // 3072
constexpr int Mrows = Bc * Sc;       // 8192

// Scratch (device globals; no allocation in kernel_launch)
__device__ float g_attn_fb[(size_t)Bc * Hc * Sc * Sc];
__device__ float g_psum[(size_t)Bc * Hc * Sc * 16];
__device__ __nv_bfloat16 g_x_hi[(size_t)Mrows * Dc],   g_x_lo[(size_t)Mrows * Dc];
__device__ __nv_bfloat16 g_wq_hi[(size_t)TD3 * Dc],    g_wq_lo[(size_t)TD3 * Dc];
__device__ __nv_bfloat16 g_wo_hi[(size_t)Dc * Dc],     g_wo_lo[(size_t)Dc * Dc];
__device__ __nv_bfloat16 g_qkv_hi[(size_t)Mrows * TD3], g_qkv_lo[(size_t)Mrows * TD3];
__device__ __nv_bfloat16 g_v_hi[(size_t)Mrows * Dc],   g_v_lo[(size_t)Mrows * Dc];

// ---------------------------------------------------------------------------
// helpers
// ---------------------------------------------------------------------------
__device__ __forceinline__ uint32_t smem_u32(const void* p) {
    uint32_t a;
    asm("{ .reg .u64 t; cvta.to.shared.u64 t, %1; cvt.u32.u64 %0, t; }"
        : "=r"(a) : "l"(p));
    return a;
}
__device__ __forceinline__ uint32_t sw64(uint32_t o)  { return o ^ ((o >> 3) & 0x30); }
__device__ __forceinline__ uint32_t sw128(uint32_t o) { return o ^ ((o >> 3) & 0x70); }

__device__ __forceinline__ void ldsm4(uint32_t a, uint32_t r[4]) {
    asm volatile("ldmatrix.sync.aligned.m8n8.x4.shared.b16 {%0,%1,%2,%3}, [%4];"
                 : "=r"(r[0]), "=r"(r[1]), "=r"(r[2]), "=r"(r[3]) : "r"(a));
}
__device__ __forceinline__ void ldsm4t(uint32_t a, uint32_t r[4]) {
    asm volatile("ldmatrix.sync.aligned.m8n8.x4.trans.shared.b16 {%0,%1,%2,%3}, [%4];"
                 : "=r"(r[0]), "=r"(r[1]), "=r"(r[2]), "=r"(r[3]) : "r"(a));
}
__device__ __forceinline__ void mma16816(float d[4], const uint32_t a[4], const uint32_t b[2]) {
    asm volatile(
        "mma.sync.aligned.m16n8k16.row.col.f32.bf16.bf16.f32 "
        "{%0,%1,%2,%3}, {%4,%5,%6,%7}, {%8,%9}, {%0,%1,%2,%3};"
        : "+f"(d[0]), "+f"(d[1]), "+f"(d[2]), "+f"(d[3])
        : "r"(a[0]), "r"(a[1]), "r"(a[2]), "r"(a[3]), "r"(b[0]), "r"(b[1]));
}
__device__ __forceinline__ void cp16(uint32_t dst, const void* src) {
    asm volatile("cp.async.cg.shared.global [%0], [%1], 16;" :: "r"(dst), "l"(src));
}
__device__ __forceinline__ void cp_commit() {
    asm volatile("cp.async.commit_group;" ::: "memory");
}
template <int N> __device__ __forceinline__ void cp_wait() {
    asm volatile("cp.async.wait_group %0;" :: "n"(N) : "memory");
}
__device__ __forceinline__ void split_hilo(float4 v, uint2& hw, uint2& lw) {
    __nv_bfloat162 h01 = __floats2bfloat162_rn(v.x, v.y);
    __nv_bfloat162 h23 = __floats2bfloat162_rn(v.z, v.w);
    float r0 = v.x - __low2float(h01);
    float r1 = v.y - __high2float(h01);
    float r2 = v.z - __low2float(h23);
    float r3 = v.w - __high2float(h23);
    __nv_bfloat162 l01 = __floats2bfloat162_rn(r0, r1);
    __nv_bfloat162 l23 = __floats2bfloat162_rn(r2, r3);
    hw.x = *reinterpret_cast<uint32_t*>(&h01); hw.y = *reinterpret_cast<uint32_t*>(&h23);
    lw.x = *reinterpret_cast<uint32_t*>(&l01); lw.y = *reinterpret_cast<uint32_t*>(&l23);
}
__device__ __forceinline__ void pack_hilo(float v0, float v1, uint32_t& h, uint32_t& l) {
    __nv_bfloat162 h2 = __floats2bfloat162_rn(v0, v1);
    float r0 = v0 - __low2float(h2), r1 = v1 - __high2float(h2);
    __nv_bfloat162 l2 = __floats2bfloat162_rn(r0, r1);
    h = *reinterpret_cast<uint32_t*>(&h2);
    l = *reinterpret_cast<uint32_t*>(&l2);
}

// ---------------------------------------------------------------------------
// merged convert kernel: three fp32 -> (hi, lo) arrays in one launch
// blocks [0,8192): x ; [8192,11264): w_qkv ; [11264,12288): w_out
// ---------------------------------------------------------------------------
__global__ __launch_bounds__(256) void cvt_hilo3(
    const float4* __restrict__ in0, uint2* __restrict__ h0, uint2* __restrict__ l0,
    const float4* __restrict__ in1, uint2* __restrict__ h1, uint2* __restrict__ l1,
    const float4* __restrict__ in2, uint2* __restrict__ h2, uint2* __restrict__ l2)
{
    const int bx = blockIdx.x;
    const float4* in; uint2 *hp, *lp; int i;
    if (bx < 8192)       { in = in0; hp = h0; lp = l0; i = bx * 256 + threadIdx.x; }
    else if (bx < 11264) { in = in1; hp = h1; lp = l1; i = (bx - 8192) * 256 + threadIdx.x; }
    else                 { in = in2; hp = h2; lp = l2; i = (bx - 11264) * 256 + threadIdx.x; }
    uint2 h, l;
    split_hilo(in[i], h, l);
    hp[i] = h; lp[i] = l;
}

// ---------------------------------------------------------------------------
// compute core: one BK=32 chunk; A,B tiles 128 rows x 64B, SW64
// ---------------------------------------------------------------------------
__device__ __forceinline__ void compute64(uint32_t sb, int wm, int wn, int lane,
                                          float acc[2][8][4]) {
    const uint32_t Ah = sb, Al = sb + 8192, Bh = sb + 16384, Bl = sb + 24576;
    const int arow = ((lane >> 3) & 1) * 8 + (lane & 7);
    const int brow = ((lane >> 4) & 1) * 8 + (lane & 7);
#pragma unroll
    for (int ks = 0; ks < 2; ks++) {
        const uint32_t akb = (uint32_t)(ks * 32 + ((lane >> 4) & 1) * 16);
        const uint32_t bkb = (uint32_t)(ks * 32 + ((lane >> 3) & 1) * 16);
        uint32_t ah[2][4], al[2][4];
#pragma unroll
        for (int mt = 0; mt < 2; mt++) {
            const uint32_t off = sw64((uint32_t)(wm + mt * 16 + arow) * 64 + akb);
            ldsm4(Ah + off, ah[mt]);
            ldsm4(Al + off, al[mt]);
        }
#pragma unroll
        for (int half = 0; half < 2; half++) {
            uint32_t bh[4][2], bl[4][2];
#pragma unroll
            for (int p = 0; p < 2; p++) {
                const uint32_t off = sw64((uint32_t)(wn + (half * 2 + p) * 16 + brow) * 64 + bkb);
                uint32_t t[4];
                ldsm4(Bh + off, t);
                bh[2*p][0]=t[0]; bh[2*p][1]=t[1]; bh[2*p+1][0]=t[2]; bh[2*p+1][1]=t[3];
                ldsm4(Bl + off, t);
                bl[2*p][0]=t[0]; bl[2*p][1]=t[1]; bl[2*p+1][0]=t[2]; bl[2*p+1][1]=t[3];
            }
#pragma unroll
            for (int nt = 0; nt < 4; nt++)
#pragma unroll
                for (int mt = 0; mt < 2; mt++) {
                    mma16816(acc[mt][half*4+nt], ah[mt], bh[nt]);
                    mma16816(acc[mt][half*4+nt], ah[mt], bl[nt]);
                    mma16816(acc[mt][half*4+nt], al[mt], bh[nt]);
                }
        }
    }
}

// cp.async one 128x32 bf16 tile (8KB), SW64 rows
__device__ __forceinline__ void cp_tile(uint32_t dst_base, const __nv_bfloat16* __restrict__ src,
                                        int K, int k0, int tid)
{
#pragma unroll
    for (int i = 0; i < 2; i++) {
        const int id = tid + 256 * i;
        const int row = id >> 2, c16 = id & 3;
        cp16(dst_base + sw64((uint32_t)row * 64 + c16 * 16),
             src + (size_t)row * K + k0 + c16 * 8);
    }
}

// ---------------------------------------------------------------------------
// GEMM: C[128x128] = A @ B^T + bias; 3-stage cp.async, 2 CTAs/SM
// ---------------------------------------------------------------------------
template <bool BF16OUT>
__global__ __launch_bounds__(256, 2) void gemm_bf16(
    const __nv_bfloat16* __restrict__ Ahg, const __nv_bfloat16* __restrict__ Alg,
    const __nv_bfloat16* __restrict__ Bhg, const __nv_bfloat16* __restrict__ Blg,
    int K, float* __restrict__ C, __nv_bfloat16* __restrict__ Chi,
    __nv_bfloat16* __restrict__ Clo, int N, const float* __restrict__ bias)
{
    extern __shared__ uint8_t sm[];
    const uint32_t sb0 = smem_u32(sm);
    const int tid = threadIdx.x, lane = tid & 31, w = tid >> 5;
    const int wm = (w & 3) * 32, wn = (w >> 2) * 64;

    Ahg += (size_t)(blockIdx.y * 128) * K;
    Alg += (size_t)(blockIdx.y * 128) * K;
    Bhg += (size_t)(blockIdx.x * 128) * K;
    Blg += (size_t)(blockIdx.x * 128) * K;

    const int NC = K >> 5;
#pragma unroll 1
    for (int s = 0; s < 2; s++) {
        const uint32_t st = sb0 + (uint32_t)s * 32768;
        cp_tile(st,          Ahg, K, s * 32, tid);
        cp_tile(st + 8192,   Alg, K, s * 32, tid);
        cp_tile(st + 16384,  Bhg, K, s * 32, tid);
        cp_tile(st + 24576,  Blg, K, s * 32, tid);
        cp_commit();
    }

    float acc[2][8][4] = {};
#pragma unroll 1
    for (int c = 0; c < NC; c++) {
        cp_wait<1>();
        __syncthreads();
        if (c + 2 < NC) {
            const uint32_t st = sb0 + (uint32_t)((c + 2) % 3) * 32768;
            cp_tile(st,          Ahg, K, (c + 2) * 32, tid);
            cp_tile(st + 8192,   Alg, K, (c + 2) * 32, tid);
            cp_tile(st + 16384,  Bhg, K, (c + 2) * 32, tid);
            cp_tile(st + 24576,  Blg, K, (c + 2) * 32, tid);
        }
        cp_commit();
        compute64(sb0 + (uint32_t)(c % 3) * 32768, wm, wn, lane, acc);
    }

    const int gr = blockIdx.y * 128 + wm + (lane >> 2);
    const int gc = blockIdx.x * 128 + wn + (lane & 3) * 2;
#pragma unroll
    for (int mt = 0; mt < 2; mt++) {
        const int r0 = gr + mt * 16;
#pragma unroll
        for (int nt = 0; nt < 8; nt++) {
            const int cc = gc + nt * 8;
            const float b0 = __ldg(bias + cc), b1 = __ldg(bias + cc + 1);
            const float v00 = acc[mt][nt][0] + b0, v01 = acc[mt][nt][1] + b1;
            const float v10 = acc[mt][nt][2] + b0, v11 = acc[mt][nt][3] + b1;
            if (BF16OUT) {
                uint32_t h, l;
                pack_hilo(v00, v01, h, l);
                *reinterpret_cast<uint32_t*>(Chi + (size_t)r0 * N + cc) = h;
                *reinterpret_cast<uint32_t*>(Clo + (size_t)r0 * N + cc) = l;
                pack_hilo(v10, v11, h, l);
                *reinterpret_cast<uint32_t*>(Chi + (size_t)(r0 + 8) * N + cc) = h;
                *reinterpret_cast<uint32_t*>(Clo + (size_t)(r0 + 8) * N + cc) = l;
            } else {
                float2 u0 = {v00, v01}, u1 = {v10, v11};
                *reinterpret_cast<float2*>(C + (size_t)r0 * N + cc) = u0;
                *reinterpret_cast<float2*>(C + (size_t)(r0 + 8) * N + cc) = u1;
            }
        }
    }
}

// ---------------------------------------------------------------------------
// Scores kernel: attn = exp((Q.K^T)*0.125) (unnormalized) + per-tile row sums
// ---------------------------------------------------------------------------
__global__ __launch_bounds__(256, 2) void scores_mma(
    const __nv_bfloat16* __restrict__ qh, const __nv_bfloat16* __restrict__ ql,
    float* __restrict__ attn, float* __restrict__ psum)
{
    extern __shared__ uint8_t sm[];
    const uint32_t sb0 = smem_u32(sm);
    const int tid = threadIdx.x, lane = tid & 31, w = tid >> 5;
    const int wm = (w & 3) * 32, wn = (w >> 2) * 64;
    const int z = blockIdx.z, b = z >> 4, h = z & 15;
    const size_t hb = (size_t)b * Sc * TD3 + h * 192;
    const __nv_bfloat16* Qh = qh + hb + (size_t)(blockIdx.y * 128) * TD3;
    const __nv_bfloat16* Ql = ql + hb + (size_t)(blockIdx.y * 128) * TD3;
    const __nv_bfloat16* Kh = qh + hb + 64 + (size_t)(blockIdx.x * 128) * TD3;
    const __nv_bfloat16* Kl = ql + hb + 64 + (size_t)(blockIdx.x * 128) * TD3;

#pragma unroll
    for (int i = 0; i < 4; i++) {
        const int id = tid + 256 * i;
        const int row = id >> 3, c16 = id & 7;
        const uint32_t d = sw128((uint32_t)row * 128 + c16 * 16);
        const size_t so = (size_t)row * TD3 + c16 * 8;
        cp16(sb0 +         d, Qh + so);
        cp16(sb0 + 16384 + d, Ql + so);
        cp16(sb0 + 32768 + d, Kh + so);
        cp16(sb0 + 49152 + d, Kl + so);
    }
    cp_commit();
    cp_wait<0>();
    __syncthreads();

    float acc[2][8][4] = {};
    {
        const uint32_t Ah = sb0, Al = sb0 + 16384, Bh = sb0 + 32768, Bl = sb0 + 49152;
        const int arow = ((lane >> 3) & 1) * 8 + (lane & 7);
        const int brow = ((lane >> 4) & 1) * 8 + (lane & 7);
#pragma unroll
        for (int ks = 0; ks < 4; ks++) {
            const uint32_t akb = (uint32_t)(ks * 32 + ((lane >> 4) & 1) * 16);
            const uint32_t bkb = (uint32_t)(ks * 32 + ((lane >> 3) & 1) * 16);
            uint32_t ah[2][4], al[2][4];
#pragma unroll
            for (int mt = 0; mt < 2; mt++) {
                const uint32_t off = sw128((uint32_t)(wm + mt * 16 + arow) * 128 + akb);
                ldsm4(Ah + off, ah[mt]);
                ldsm4(Al + off, al[mt]);
            }
#pragma unroll
            for (int half = 0; half < 2; half++) {
                uint32_t bh[4][2], bl[4][2];
#pragma unroll
                for (int p = 0; p < 2; p++) {
                    const uint32_t off = sw128((uint32_t)(wn + (half * 2 + p) * 16 + brow) * 128 + bkb);
                    uint32_t t[4];
                    ldsm4(Bh + off, t);
                    bh[2*p][0]=t[0]; bh[2*p][1]=t[1]; bh[2*p+1][0]=t[2]; bh[2*p+1][1]=t[3];
                    ldsm4(Bl + off, t);
                    bl[2*p][0]=t[0]; bl[2*p][1]=t[1]; bl[2*p+1][0]=t[2]; bl[2*p+1][1]=t[3];
                }
#pragma unroll
                for (int nt = 0; nt < 4; nt++)
#pragma unroll
                    for (int mt = 0; mt < 2; mt++) {
                        mma16816(acc[mt][half*4+nt], ah[mt], bh[nt]);
                        mma16816(acc[mt][half*4+nt], ah[mt], bl[nt]);
                        mma16816(acc[mt][half*4+nt], al[mt], bh[nt]);
                    }
            }
        }
    }
    __syncthreads();

    float* smf = reinterpret_cast<float*>(sm);
    const int r0 = wm + (lane >> 2);
    const int c0 = wn + (lane & 3) * 2;
#pragma unroll
    for (int mt = 0; mt < 2; mt++) {
#pragma unroll
        for (int nt = 0; nt < 8; nt++) {
            const int cc = c0 + nt * 8;
            smf[(r0 + mt * 16) * 128 + cc]     = __expf(acc[mt][nt][0] * 0.125f);
            smf[(r0 + mt * 16) * 128 + cc + 1] = __expf(acc[mt][nt][1] * 0.125f);
            smf[(r0 + mt * 16 + 8) * 128 + cc]     = __expf(acc[mt][nt][2] * 0.125f);
            smf[(r0 + mt * 16 + 8) * 128 + cc + 1] = __expf(acc[mt][nt][3] * 0.125f);
        }
    }
    __syncthreads();

    if (tid < 128) {
        float s = 0.f;
#pragma unroll 8
        for (int j = 0; j < 128; j++) s += smf[tid * 128 + ((j + tid) & 127)];
        psum[((size_t)z * Sc + blockIdx.y * 128 + tid) * 16 + blockIdx.x] = s;
    }

    float* cbase = attn + (size_t)z * Sc * Sc + (size_t)(blockIdx.y * 128) * Sc
                 + blockIdx.x * 128;
    const float4* s4 = reinterpret_cast<const float4*>(sm);
#pragma unroll
    for (int i = 0; i < 16; i++) {
        const int id = tid + 256 * i;
        const int row = id >> 5, u = id & 31;
        *reinterpret_cast<float4*>(cbase + (size_t)row * Sc + u * 4) = s4[id];
    }
}

// ---------------------------------------------------------------------------
// PV: fully async pipeline.
// smem: A fp32 staging 2x16KB @0 ; A bf16 MMA bufs 2x16KB @32768 ;
//       V bf16 3x8KB @65536 ; invs @90112
// ---------------------------------------------------------------------------
constexpr uint32_t PV_AST = 0;
constexpr uint32_t PV_AB  = 32768;
constexpr uint32_t PV_V   = 65536;
constexpr uint32_t PV_INV = 90112;
constexpr uint32_t PV_SMEM = 90624;

__device__ __forceinline__ void computePV(uint32_t ab, uint32_t vb, int wm, int wn, int lane,
                                          float acc[2][4][4]) {
    const uint32_t Ah = ab, Al = ab + 8192, Vh = vb, Vl = vb + 4096;
    const int arow = ((lane >> 3) & 1) * 8 + (lane & 7);
    const int krw  = ((lane >> 3) & 1) * 8 + (lane & 7);
    const int dof  = ((lane >> 4) & 1) * 8;
#pragma unroll
    for (int ks = 0; ks < 2; ks++) {
        const uint32_t akb = (uint32_t)(ks * 32 + ((lane >> 4) & 1) * 16);
        uint32_t ah[2][4], al[2][4];
#pragma unroll
        for (int mt = 0; mt < 2; mt++) {
            const uint32_t off = sw64((uint32_t)(wm + mt * 16 + arow) * 64 + akb);
            ldsm4(Ah + off, ah[mt]);
            ldsm4(Al + off, al[mt]);
        }
        uint32_t vh[4][2], vl[4][2];
#pragma unroll
        for (int p = 0; p < 2; p++) {
            const uint32_t off = sw128((uint32_t)(ks * 16 + krw) * 128 +
                                       (uint32_t)(wn + p * 16 + dof) * 2);
            uint32_t t[4];
            ldsm4t(Vh + off, t);
            vh[2*p][0]=t[0]; vh[2*p][1]=t[1]; vh[2*p+1][0]=t[2]; vh[2*p+1][1]=t[3];
            ldsm4t(Vl + off, t);
            vl[2*p][0]=t[0]; vl[2*p][1]=t[1]; vl[2*p+1][0]=t[2]; vl[2*p+1][1]=t[3];
        }
#pragma unroll
        for (int nt = 0; nt < 4; nt++)
#pragma unroll
            for (int mt = 0; mt < 2; mt++) {
                mma16816(acc[mt][nt], ah[mt], vh[nt]);
                mma16816(acc[mt][nt], ah[mt], vl[nt]);
                mma16816(acc[mt][nt], al[mt], vh[nt]);
            }
    }
}

__global__ __launch_bounds__(256, 2) void pv_mma(
    float* __restrict__ attn, const __nv_bfloat16* __restrict__ qh,
    const __nv_bfloat16* __restrict__ ql, const float* __restrict__ psum,
    __nv_bfloat16* __restrict__ voh, __nv_bfloat16* __restrict__ vol)
{
    extern __shared__ uint8_t sm[];
    const uint32_t sb0 = smem_u32(sm);
    float* invs = reinterpret_cast<float*>(sm + PV_INV);
    const int tid = threadIdx.x, lane = tid & 31, w = tid >> 5;
    const int wm = (w & 3) * 32, wn = (w >> 2) * 32;

    const int z = blockIdx.y, b = z >> 4, h = z & 15;
    const int qt = blockIdx.x;
    float* A = attn + (size_t)z * Sc * Sc + (size_t)(qt * 128) * Sc;
    const __nv_bfloat16* Vh = qh + (size_t)b * Sc * TD3 + h * 192 + 128;
    const __nv_bfloat16* Vl = ql + (size_t)b * Sc * TD3 + h * 192 + 128;

    // per-thread A region: row = tid>>1, 16 floats at col (tid&1)*16
    const int arow = tid >> 1, acol = (tid & 1) * 16;
    const uint32_t abase = (uint32_t)arow * 128 + (uint32_t)(tid & 1) * 64;
    // V cp mapping
    const int vrow = tid >> 3, vc16 = tid & 7;
    const uint32_t vdst = sw128((uint32_t)vrow * 128 + vc16 * 16);

    // prologue: prefetch chunks 0 and 1 (A staging + V), each one commit group
#pragma unroll
    for (int s = 0; s < 2; s++) {
        const uint32_t ast = sb0 + PV_AST + (uint32_t)s * 16384;
        const float* asrc = A + (size_t)arow * Sc + s * 32 + acol;
#pragma unroll
        for (int i = 0; i < 4; i++)
            cp16(ast + sw128(abase + i * 16), asrc + i * 4);
        const uint32_t vb = sb0 + PV_V + (uint32_t)s * 8192;
        const size_t so = (size_t)(s * 32 + vrow) * TD3 + vc16 * 8;
        cp16(vb + vdst, Vh + so);
        cp16(vb + 4096 + vdst, Vl + so);
        cp_commit();
    }
    if (tid < 128) {
        const float* pp = psum + ((size_t)z * Sc + qt * 128 + tid) * 16;
        float s = 0.f;
#pragma unroll
        for (int j = 0; j < 16; j++) s += pp[j];
        invs[tid] = 1.f / s;
    }
    __syncthreads();
    const float inv = invs[arow];

    float acc[2][4][4] = {};
#pragma unroll 1
    for (int c = 0; c < 64; c++) {
        cp_wait<1>();
        const uint32_t ast = sb0 + PV_AST + (uint32_t)(c & 1) * 16384;
        const uint32_t ab  = sb0 + PV_AB  + (uint32_t)(c & 1) * 16384;
        // consume own staging region: scale, STG normalized, pack bf16
        float* aout = A + (size_t)arow * Sc + c * 32 + acol;
#pragma unroll
        for (int i = 0; i < 4; i++) {
            float4 v = *reinterpret_cast<const float4*>(sm + PV_AST + (uint32_t)(c & 1) * 16384
                                                        + sw128(abase + i * 16));
            v.x *= inv; v.y *= inv; v.z *= inv; v.w *= inv;
            *reinterpret_cast<float4*>(aout + i * 4) = v;
            uint2 hw, lw;
            split_hilo(v, hw, lw);
            const uint32_t swo = sw64(abase / 2 + i * 8);
            *reinterpret_cast<uint2*>(sm + (ab - sb0) + swo) = hw;
            *reinterpret_cast<uint2*>(sm + (ab - sb0) + 8192 + swo) = lw;
        }
        // prefetch chunk c+2 (A into staging slot (c&1), V into slot (c+2)%3)
        if (c + 2 < 64) {
            const float* asrc = A + (size_t)arow * Sc + (c + 2) * 32 + acol;
#pragma unroll
            for (int i = 0; i < 4; i++)
                cp16(ast + sw128(abase + i * 16), asrc + i * 4);
            const uint32_t vb = sb0 + PV_V + (uint32_t)((c + 2) % 3) * 8192;
            const size_t so = (size_t)((c + 2) * 32 + vrow) * TD3 + vc16 * 8;
            cp16(vb + vdst, Vh + so);
            cp16(vb + 4096 + vdst, Vl + so);
        }
        cp_commit();
        __syncthreads();
        computePV(ab, sb0 + PV_V + (uint32_t)(c % 3) * 8192, wm, wn, lane, acc);
    }

    __nv_bfloat16* Oh = voh + (size_t)z * Sc * HDc + (size_t)(qt * 128) * HDc;
    __nv_bfloat16* Ol = vol + (size_t)z * Sc * HDc + (size_t)(qt * 128) * HDc;
    const int r0b = wm + (lane >> 2);
    const int ccb = wn + (lane & 3) * 2;
#pragma unroll
    for (int mt = 0; mt < 2; mt++) {
        const int r0 = r0b + mt * 16;
#pragma unroll
        for (int nt = 0; nt < 4; nt++) {
            const int cc = ccb + nt * 8;
            uint32_t hh, ll;
            pack_hilo(acc[mt][nt][0], acc[mt][nt][1], hh, ll);
            *reinterpret_cast<uint32_t*>(Oh + (size_t)r0 * HDc + cc) = hh;
            *reinterpret_cast<uint32_t*>(Ol + (size_t)r0 * HDc + cc) = ll;
            pack_hilo(acc[mt][nt][2], acc[mt][nt][3], hh, ll);
            *reinterpret_cast<uint32_t*>(Oh + (size_t)(r0 + 8) * HDc + cc) = hh;
            *reinterpret_cast<uint32_t*>(Ol + (size_t)(r0 + 8) * HDc + cc) = ll;
        }
    }
}

// ---------------------------------------------------------------------------
extern "C" void kernel_launch(void* const* d_in, const int* in_sizes, int n_in,
                              void* d_out, int out_size)
{
    const float* x     = (const float*)d_in[0];
    const float* w_qkv = (const float*)d_in[1];
    const float* b_qkv = (const float*)d_in[2];
    const float* w_out = (const float*)d_in[3];
    const float* b_out = (const float*)d_in[4];
    float* out = (float*)d_out;

    const size_t BSD  = (size_t)Bc * Sc * Dc;
    const size_t BHSS = (size_t)Bc * Hc * Sc * Sc;

    float *attn_fb, *psum;
    cudaGetSymbolAddress((void**)&attn_fb, g_attn_fb);
    cudaGetSymbolAddress((void**)&psum,    g_psum);
    __nv_bfloat16 *xh, *xl, *wqh, *wql, *woh, *wol, *qkvh, *qkvl, *vh, *vl;
    cudaGetSymbolAddress((void**)&xh,   g_x_hi);   cudaGetSymbolAddress((void**)&xl,   g_x_lo);
    cudaGetSymbolAddress((void**)&wqh,  g_wq_hi);  cudaGetSymbolAddress((void**)&wql,  g_wq_lo);
    cudaGetSymbolAddress((void**)&woh,  g_wo_hi);  cudaGetSymbolAddress((void**)&wol,  g_wo_lo);
    cudaGetSymbolAddress((void**)&qkvh, g_qkv_hi); cudaGetSymbolAddress((void**)&qkvl, g_qkv_lo);
    cudaGetSymbolAddress((void**)&vh,   g_v_hi);   cudaGetSymbolAddress((void**)&vl,   g_v_lo);

    float* attn = ((size_t)out_size >= BSD + BHSS) ? (out + BSD) : attn_fb;

    cudaFuncSetAttribute(gemm_bf16<true>,  cudaFuncAttributeMaxDynamicSharedMemorySize, 98304);
    cudaFuncSetAttribute(gemm_bf16<false>, cudaFuncAttributeMaxDynamicSharedMemorySize, 98304);
    cudaFuncSetAttribute(scores_mma,       cudaFuncAttributeMaxDynamicSharedMemorySize, 65536);
    cudaFuncSetAttribute(pv_mma,           cudaFuncAttributeMaxDynamicSharedMemorySize, PV_SMEM);

    // 0) pre-split fp32 -> bf16 hi/lo (one merged launch)
    cvt_hilo3<<<12288, 256>>>(
        (const float4*)x,     (uint2*)xh,  (uint2*)xl,
        (const float4*)w_qkv, (uint2*)wqh, (uint2*)wql,
        (const float4*)w_out, (uint2*)woh, (uint2*)wol);

    // 1) fused QKV projection -> bf16 hi/lo qkv directly
    gemm_bf16<true><<<dim3(TD3 / 128, Mrows / 128), 256, 98304>>>(
        xh, xl, wqh, wql, Dc, nullptr, qkvh, qkvl, TD3, b_qkv);

    // 2) attention scores: exp(QK/8) + per-tile row sums
    scores_mma<<<dim3(Sc / 128, Sc / 128, Bc * Hc), 256, 65536>>>(qkvh, qkvl, attn, psum);

    // 3) PV: normalize attn in place + vals = attn_norm @ V (writes vals hi/lo)
    pv_mma<<<dim3(Sc / 128, Bc * Hc), 256, PV_SMEM>>>(attn, qkvh, qkvl, psum, vh, vl);

    // 4) output projection: out = vals @ w_out^T + b_out
    gemm_bf16<false><<<dim3(Dc / 128, Mrows / 128), 256, 98304>>>(
        vh, vl, woh, wol, Dc, out, nullptr, nullptr, Dc, b_out);
}